// round 3
// baseline (speedup 1.0000x reference)
#include <cuda_runtime.h>
#include <cstdint>

#define NB     2048
#define NPAR   66048

// Scratch (device globals; allocation is forbidden)
__device__ __align__(16) float g_G [NB * 1024];  // X@Wk precomputed gates
__device__ __align__(16) float g_H [NB * 256];   // LSTM hidden outputs
__device__ __align__(16) float g_X3[NB * 256];   // post dense_0

__device__ __forceinline__ float sigf(float x) { return 1.0f / (1.0f + __expf(-x)); }

__device__ __forceinline__ float2 fma2(float2 a, float2 b, float2 c) {
    unsigned long long A, Bv, C, D;
    asm("mov.b64 %0, {%1,%2};" : "=l"(A)  : "f"(a.x), "f"(a.y));
    asm("mov.b64 %0, {%1,%2};" : "=l"(Bv) : "f"(b.x), "f"(b.y));
    asm("mov.b64 %0, {%1,%2};" : "=l"(C)  : "f"(c.x), "f"(c.y));
    asm("fma.rn.f32x2 %0, %1, %2, %3;" : "=l"(D) : "l"(A), "l"(Bv), "l"(C));
    float2 r;
    asm("mov.b64 {%0,%1}, %2;" : "=f"(r.x), "=f"(r.y) : "l"(D));
    return r;
}

__device__ __forceinline__ unsigned smem_u32(const void* p) {
    unsigned a;
    asm("{ .reg .u64 t; cvta.to.shared.u64 t, %1; cvt.u32.u64 %0, t; }" : "=r"(a) : "l"(p));
    return a;
}

// ===== Kernel A: cond path + dense_in + G = x_in @ Wk. 128 CTAs x 16 rows =====
__global__ __launch_bounds__(256) void kA(
    const float* __restrict__ actions, const float* __restrict__ obs,
    const float* __restrict__ Wci, const float* __restrict__ vci,
    const float* __restrict__ gci, const float* __restrict__ bci,
    const float* __restrict__ Wcl, const float* __restrict__ bcl,
    const float* __restrict__ Win, const float* __restrict__ vin,
    const float* __restrict__ gin, const float* __restrict__ bin,
    const float* __restrict__ Wk)
{
    __shared__ float sm1[16 * 256];
    __shared__ float sm2[16 * 256];
    const int tid = threadIdx.x;
    const int r0  = blockIdx.x * 16;

    { // t1 = actions @ Wci -> sm1[16][64]
        const int j = tid & 63, rr = tid >> 6;
        #pragma unroll
        for (int q = 0; q < 4; q++) {
            const int r = rr + q * 4;
            float acc = 0.f;
            #pragma unroll
            for (int k = 0; k < 16; k++)
                acc += actions[(r0 + r) * 16 + k] * Wci[k * 64 + j];
            sm1[r * 64 + j] = acc;
        }
    }
    __syncthreads();
    { // evonorm(groups=8) -> sm2[16][64]
        const int j = tid & 63, rr = tid >> 6;
        const float v = vci[j], g = gci[j], bb = bci[j];
        #pragma unroll
        for (int q = 0; q < 4; q++) {
            const int r = rr + q * 4;
            const float* row = &sm1[r * 64 + (j & ~7)];
            float s1 = 0.f, s2 = 0.f;
            #pragma unroll
            for (int e = 0; e < 8; e++) { float t = row[e]; s1 += t; s2 += t * t; }
            const float mean = s1 * 0.125f;
            const float var  = s2 * 0.125f - mean * mean;
            const float x = sm1[r * 64 + j];
            sm2[r * 64 + j] = x * sigf(v * x) / sqrtf(var + 1e-5f) * g + bb;
        }
    }
    __syncthreads();
    { // x = a1 @ Wcl + bcl + obs -> sm1[16][64]
        const int j = tid & 63, rr = tid >> 6;
        const float bj = bcl[j];
        float acc[4];
        #pragma unroll
        for (int q = 0; q < 4; q++)
            acc[q] = bj + obs[(r0 + rr + q * 4) * 64 + j];
        for (int k = 0; k < 64; k++) {
            const float w = Wcl[k * 64 + j];
            #pragma unroll
            for (int q = 0; q < 4; q++)
                acc[q] += sm2[(rr + q * 4) * 64 + k] * w;
        }
        #pragma unroll
        for (int q = 0; q < 4; q++)
            sm1[(rr + q * 4) * 64 + j] = acc[q];
    }
    __syncthreads();
    { // t2 = x @ Win -> sm2[16][256]
        const int j = tid;
        float acc[16];
        #pragma unroll
        for (int r = 0; r < 16; r++) acc[r] = 0.f;
        for (int k = 0; k < 64; k++) {
            const float w = Win[k * 256 + j];
            #pragma unroll
            for (int r = 0; r < 16; r++) acc[r] += sm1[r * 64 + k] * w;
        }
        #pragma unroll
        for (int r = 0; r < 16; r++) sm2[r * 256 + j] = acc[r];
    }
    __syncthreads();
    { // evonorm(groups=32 -> size 8) -> sm1[16][256]
        const int j = tid;
        const float v = vin[j], g = gin[j], bb = bin[j];
        for (int r = 0; r < 16; r++) {
            const float* row = &sm2[r * 256 + (j & ~7)];
            float s1 = 0.f, s2 = 0.f;
            #pragma unroll
            for (int e = 0; e < 8; e++) { float t = row[e]; s1 += t; s2 += t * t; }
            const float mean = s1 * 0.125f;
            const float var  = s2 * 0.125f - mean * mean;
            const float x = sm2[r * 256 + j];
            sm1[r * 256 + j] = x * sigf(v * x) / sqrtf(var + 1e-5f) * g + bb;
        }
    }
    __syncthreads();
    { // G = x_in @ Wk  (thread: 4 cols x 16 rows)
        const int c0 = tid * 4;
        float2 acc[16][2];
        #pragma unroll
        for (int r = 0; r < 16; r++) { acc[r][0] = make_float2(0.f,0.f); acc[r][1] = make_float2(0.f,0.f); }
        for (int k = 0; k < 256; k++) {
            const float4 w4 = *(const float4*)&Wk[k * 1024 + c0];
            const float2 wa = make_float2(w4.x, w4.y);
            const float2 wb = make_float2(w4.z, w4.w);
            #pragma unroll
            for (int r = 0; r < 16; r++) {
                const float x = sm1[r * 256 + k];
                const float2 xx = make_float2(x, x);
                acc[r][0] = fma2(wa, xx, acc[r][0]);
                acc[r][1] = fma2(wb, xx, acc[r][1]);
            }
        }
        #pragma unroll
        for (int r = 0; r < 16; r++) {
            float4 o;
            o.x = acc[r][0].x; o.y = acc[r][0].y; o.z = acc[r][1].x; o.w = acc[r][1].y;
            *(float4*)&g_G[(size_t)(r0 + r) * 1024 + c0] = o;
        }
    }
}

// ===== Kernel B: sequential LSTM, one 8-CTA cluster, 512 thr/CTA ============
__global__ void __launch_bounds__(512, 1) __cluster_dims__(8, 1, 1)
kB(const float* __restrict__ Wr, const float* __restrict__ vl_,
   const float* __restrict__ gl_, const float* __restrict__ bl_)
{
    __shared__ __align__(16) float s_h[256];
    __shared__ __align__(16) float s_z[2][128];

    const int tid = threadIdx.x;
    unsigned rank;
    asm("mov.u32 %0, %%cluster_ctarank;" : "=r"(rank));

    const int lcol  = tid >> 2;              // 0..127
    const int kpart = tid & 3;               // 0..3
    const int gcol  = (int)rank * 128 + lcol;
    const int k0    = kpart * 64;

    float2 wv[32];
    #pragma unroll
    for (int i = 0; i < 32; i++) {
        wv[i].x = Wr[(size_t)(k0 + 2*i)     * 1024 + gcol];
        wv[i].y = Wr[(size_t)(k0 + 2*i + 1) * 1024 + gcol];
    }

    float vl = 0.f, gl = 0.f, bl = 0.f, cst = 0.f;
    unsigned za0=0,za1=0,za2=0,za3=0, zb0=0,zb1=0,zb2=0,zb3=0;
    if (tid < 256) {
        vl = vl_[tid]; gl = gl_[tid]; bl = bl_[tid];
        #pragma unroll
        for (int g2 = 0; g2 < 4; g2++) {
            const int col = g2 * 256 + tid;
            const unsigned owner = (unsigned)(col >> 7);
            const unsigned local = (unsigned)(col & 127);
            unsigned la0 = smem_u32(&s_z[0][local]);
            unsigned la1 = smem_u32(&s_z[1][local]);
            unsigned ra0, ra1;
            asm("mapa.shared::cluster.u32 %0, %1, %2;" : "=r"(ra0) : "r"(la0), "r"(owner));
            asm("mapa.shared::cluster.u32 %0, %1, %2;" : "=r"(ra1) : "r"(la1), "r"(owner));
            if (g2 == 0) { za0 = ra0; zb0 = ra1; }
            if (g2 == 1) { za1 = ra0; zb1 = ra1; }
            if (g2 == 2) { za2 = ra0; zb2 = ra1; }
            if (g2 == 3) { za3 = ra0; zb3 = ra1; }
        }
        s_h[tid] = 0.f;
    }
    __syncthreads();

    int p = 0;
    for (int t = 0; t < NB; t++) {
        float gt = 0.f;
        if (kpart == 0) gt = g_G[(size_t)t * 1024 + gcol];

        float2 a0 = make_float2(0.f,0.f), a1 = make_float2(0.f,0.f);
        const float4* h4 = (const float4*)(s_h + k0);
        #pragma unroll
        for (int i = 0; i < 16; i++) {
            const float4 h = h4[i];
            a0 = fma2(wv[2*i],   make_float2(h.x, h.y), a0);
            a1 = fma2(wv[2*i+1], make_float2(h.z, h.w), a1);
        }
        float sum = a0.x + a0.y + a1.x + a1.y;
        sum += __shfl_xor_sync(0xffffffffu, sum, 1);
        sum += __shfl_xor_sync(0xffffffffu, sum, 2);
        if (kpart == 0) s_z[p][lcol] = sum + gt;

        asm volatile("barrier.cluster.arrive.aligned;" ::: "memory");
        asm volatile("barrier.cluster.wait.aligned;"   ::: "memory");

        if (tid < 256) {
            const unsigned ai = p ? zb0 : za0;
            const unsigned af = p ? zb1 : za1;
            const unsigned ac = p ? zb2 : za2;
            const unsigned ao = p ? zb3 : za3;
            float zi, zf, zc, zo;
            asm volatile("ld.shared::cluster.f32 %0, [%1];" : "=f"(zi) : "r"(ai));
            asm volatile("ld.shared::cluster.f32 %0, [%1];" : "=f"(zf) : "r"(af));
            asm volatile("ld.shared::cluster.f32 %0, [%1];" : "=f"(zc) : "r"(ac));
            asm volatile("ld.shared::cluster.f32 %0, [%1];" : "=f"(zo) : "r"(ao));

            float s1 = zc, s2 = zc * zc;
            s1 += __shfl_xor_sync(0xffffffffu, s1, 1);  s2 += __shfl_xor_sync(0xffffffffu, s2, 1);
            s1 += __shfl_xor_sync(0xffffffffu, s1, 2);  s2 += __shfl_xor_sync(0xffffffffu, s2, 2);
            s1 += __shfl_xor_sync(0xffffffffu, s1, 4);  s2 += __shfl_xor_sync(0xffffffffu, s2, 4);
            float mean = s1 * 0.125f;
            float var  = s2 * 0.125f - mean * mean;
            const float ecc = zc * sigf(vl * zc) / sqrtf(var + 1e-5f) * gl + bl;

            cst = sigf(zf) * cst + sigf(zi) * ecc;

            s1 = cst; s2 = cst * cst;
            s1 += __shfl_xor_sync(0xffffffffu, s1, 1);  s2 += __shfl_xor_sync(0xffffffffu, s2, 1);
            s1 += __shfl_xor_sync(0xffffffffu, s1, 2);  s2 += __shfl_xor_sync(0xffffffffu, s2, 2);
            s1 += __shfl_xor_sync(0xffffffffu, s1, 4);  s2 += __shfl_xor_sync(0xffffffffu, s2, 4);
            mean = s1 * 0.125f;
            var  = s2 * 0.125f - mean * mean;
            const float ecn = cst * sigf(vl * cst) / sqrtf(var + 1e-5f) * gl + bl;

            const float h = sigf(zo) * ecn;
            if (rank == 0) g_H[(size_t)t * 256 + tid] = h;
            s_h[tid] = h;
        }
        __syncthreads();
        p ^= 1;
    }
    asm volatile("barrier.cluster.arrive.aligned;" ::: "memory");
    asm volatile("barrier.cluster.wait.aligned;"   ::: "memory");
}

// ===== Kernel C: dense_0 + evonorm -> g_X3 ==================================
__global__ __launch_bounds__(256) void kC(
    const float* __restrict__ Wd0, const float* __restrict__ vd,
    const float* __restrict__ gd,  const float* __restrict__ bd)
{
    __shared__ float sm1[16 * 256];
    __shared__ float sm2[16 * 256];
    const int tid = threadIdx.x;
    const int r0  = blockIdx.x * 16;

    const float4* src = (const float4*)(g_H + (size_t)r0 * 256);
    for (int i = tid; i < 1024; i += 256)
        ((float4*)sm1)[i] = src[i];
    __syncthreads();

    const int j = tid;
    float acc[16];
    #pragma unroll
    for (int r = 0; r < 16; r++) acc[r] = 0.f;
    for (int k4 = 0; k4 < 64; k4++) {
        const int k = k4 * 4;
        const float w0 = Wd0[(k+0)*256 + j];
        const float w1 = Wd0[(k+1)*256 + j];
        const float w2 = Wd0[(k+2)*256 + j];
        const float w3 = Wd0[(k+3)*256 + j];
        #pragma unroll
        for (int r = 0; r < 16; r++) {
            const float4 x = *(const float4*)&sm1[r * 256 + k];
            acc[r] += x.x*w0 + x.y*w1 + x.z*w2 + x.w*w3;
        }
    }
    #pragma unroll
    for (int r = 0; r < 16; r++) sm2[r * 256 + j] = acc[r];
    __syncthreads();

    const float v = vd[j], g = gd[j], bb = bd[j];
    for (int r = 0; r < 16; r++) {
        const float* row = &sm2[r * 256 + (j & ~7)];
        float s1 = 0.f, s2 = 0.f;
        #pragma unroll
        for (int e = 0; e < 8; e++) { float t = row[e]; s1 += t; s2 += t * t; }
        const float mean = s1 * 0.125f;
        const float var  = s2 * 0.125f - mean * mean;
        const float x = sm2[r * 256 + j];
        g_X3[(size_t)(r0 + r) * 256 + j] = x * sigf(v * x) / sqrtf(var + 1e-5f) * g + bb;
    }
}

// ===== Kernel D: OUT = X3 @ W_out + b_out, 128x128 tiles ====================
__global__ __launch_bounds__(256) void kD(
    const float* __restrict__ Wout, const float* __restrict__ bout,
    float* __restrict__ out)
{
    extern __shared__ float sx[];           // [128][256] = 128 KB
    const int tid = threadIdx.x;
    const int c0  = blockIdx.x * 128;
    const int r0  = blockIdx.y * 128;

    const float4* src = (const float4*)(g_X3 + (size_t)r0 * 256);
    for (int i = tid; i < 8192; i += 256)
        ((float4*)sx)[i] = src[i];
    __syncthreads();

    const int cp = tid & 63;
    const int rg = tid >> 6;
    const int c  = c0 + cp * 2;
    const float* wbase = Wout + c;

    float2 acc[32];
    #pragma unroll
    for (int r = 0; r < 32; r++) acc[r] = make_float2(0.f, 0.f);

    float2 wcur[4];
    #pragma unroll
    for (int u = 0; u < 4; u++)
        wcur[u] = *(const float2*)(wbase + (size_t)u * NPAR);

    for (int k = 0; k < 256; k += 4) {
        float2 wnext[4];
        if (k + 4 < 256) {
            #pragma unroll
            for (int u = 0; u < 4; u++)
                wnext[u] = *(const float2*)(wbase + (size_t)(k + 4 + u) * NPAR);
        }
        #pragma unroll
        for (int r = 0; r < 32; r++) {
            const float4 xv = *(const float4*)&sx[(rg * 32 + r) * 256 + k];
            acc[r] = fma2(wcur[0], make_float2(xv.x, xv.x), acc[r]);
            acc[r] = fma2(wcur[1], make_float2(xv.y, xv.y), acc[r]);
            acc[r] = fma2(wcur[2], make_float2(xv.z, xv.z), acc[r]);
            acc[r] = fma2(wcur[3], make_float2(xv.w, xv.w), acc[r]);
        }
        #pragma unroll
        for (int u = 0; u < 4; u++) wcur[u] = wnext[u];
    }

    const float2 bb = *(const float2*)&bout[c];
    #pragma unroll
    for (int r = 0; r < 32; r++) {
        float2 v;
        v.x = acc[r].x + bb.x;
        v.y = acc[r].y + bb.y;
        *(float2*)&out[(size_t)(r0 + rg * 32 + r) * NPAR + c] = v;
    }
}

// ============================================================================
extern "C" void kernel_launch(void* const* d_in, const int* in_sizes, int n_in,
                              void* d_out, int out_size)
{
    const float* actions = (const float*)d_in[0];
    const float* obs     = (const float*)d_in[1];
    const float* Wci     = (const float*)d_in[2];
    const float* vci     = (const float*)d_in[3];
    const float* gci     = (const float*)d_in[4];
    const float* bci     = (const float*)d_in[5];
    const float* Wcl     = (const float*)d_in[6];
    const float* bcl     = (const float*)d_in[7];
    const float* Win     = (const float*)d_in[8];
    const float* vin     = (const float*)d_in[9];
    const float* gin     = (const float*)d_in[10];
    const float* bin     = (const float*)d_in[11];
    const float* Wk      = (const float*)d_in[12];
    const float* Wr      = (const float*)d_in[13];
    const float* vl      = (const float*)d_in[14];
    const float* gl      = (const float*)d_in[15];
    const float* bl      = (const float*)d_in[16];
    const float* Wd0     = (const float*)d_in[17];
    const float* vd0     = (const float*)d_in[18];
    const float* gd0     = (const float*)d_in[19];
    const float* bd0     = (const float*)d_in[20];
    const float* Wout    = (const float*)d_in[21];
    const float* bout    = (const float*)d_in[22];
    float* out = (float*)d_out;

    kA<<<128, 256>>>(actions, obs, Wci, vci, gci, bci, Wcl, bcl,
                     Win, vin, gin, bin, Wk);
    kB<<<8, 512>>>(Wr, vl, gl, bl);
    kC<<<128, 256>>>(Wd0, vd0, gd0, bd0);

    cudaFuncSetAttribute(kD, cudaFuncAttributeMaxDynamicSharedMemorySize, 131072);
    dim3 gD(NPAR / 128, NB / 128);
    kD<<<gD, 256, 131072>>>(Wout, bout, out);
}

// round 6
// speedup vs baseline: 1.2201x; 1.2201x over previous
#include <cuda_runtime.h>
#include <cuda_bf16.h>
#include <cstdint>

#define NB     2048
#define NPAR   66048

// Scratch (device globals; allocation is forbidden)
__device__ __align__(16) float g_G [NB * 1024];            // X@Wk precomputed gates
__device__ __align__(16) float g_H [NB * 256];             // LSTM hidden outputs
__device__ __align__(16) __nv_bfloat16 g_Ah[NB * 256];     // X3 hi (bf16 split)
__device__ __align__(16) __nv_bfloat16 g_Al[NB * 256];     // X3 lo
__device__ __align__(16) __nv_bfloat16 g_Bh[(size_t)NPAR * 256]; // W^T hi, K-major [n][k]
__device__ __align__(16) __nv_bfloat16 g_Bl[(size_t)NPAR * 256]; // W^T lo

__device__ __forceinline__ float sigf(float x) { return 1.0f / (1.0f + __expf(-x)); }

__device__ __forceinline__ float2 fma2(float2 a, float2 b, float2 c) {
    unsigned long long A, Bv, C, D;
    asm("mov.b64 %0, {%1,%2};" : "=l"(A)  : "f"(a.x), "f"(a.y));
    asm("mov.b64 %0, {%1,%2};" : "=l"(Bv) : "f"(b.x), "f"(b.y));
    asm("mov.b64 %0, {%1,%2};" : "=l"(C)  : "f"(c.x), "f"(c.y));
    asm("fma.rn.f32x2 %0, %1, %2, %3;" : "=l"(D) : "l"(A), "l"(Bv), "l"(C));
    float2 r;
    asm("mov.b64 {%0,%1}, %2;" : "=f"(r.x), "=f"(r.y) : "l"(D));
    return r;
}

__device__ __forceinline__ unsigned smem_u32(const void* p) {
    unsigned a;
    asm("{ .reg .u64 t; cvta.to.shared.u64 t, %1; cvt.u32.u64 %0, t; }" : "=r"(a) : "l"(p));
    return a;
}

// ---- async-copy / HMMA helpers ---------------------------------------------
#define SWZ(x) ((x) ^ (((x) >> 3) & 0x70))

#define CP_ASYNC16(dst, src) \
    asm volatile("cp.async.cg.shared.global [%0], [%1], 16;" :: "r"(dst), "l"(src) : "memory")
#define CP_COMMIT()  asm volatile("cp.async.commit_group;" ::: "memory")
#define CP_WAIT_ALL() asm volatile("cp.async.wait_all;" ::: "memory")

#define LDSM_X4(r0, r1, r2, r3, addr) \
    asm volatile("ldmatrix.sync.aligned.m8n8.x4.shared.b16 {%0,%1,%2,%3}, [%4];" \
                 : "=r"(r0), "=r"(r1), "=r"(r2), "=r"(r3) : "r"(addr))

#define MMA16816(d, a, b0, b1) \
    asm volatile("mma.sync.aligned.m16n8k16.row.col.f32.bf16.bf16.f32 " \
                 "{%0,%1,%2,%3}, {%4,%5,%6,%7}, {%8,%9}, {%0,%1,%2,%3};" \
                 : "+f"((d)[0]), "+f"((d)[1]), "+f"((d)[2]), "+f"((d)[3]) \
                 : "r"((a)[0]), "r"((a)[1]), "r"((a)[2]), "r"((a)[3]), \
                   "r"(b0), "r"(b1))

// ===== Kernel W: split+transpose W_out -> g_Bh/g_Bl K-major =================
__global__ __launch_bounds__(256) void kW(const float* __restrict__ Wout)
{
    __shared__ float sm[32 * 257];
    const int tid = threadIdx.x;
    const int n0  = blockIdx.x * 32;

    #pragma unroll 4
    for (int it = 0; it < 32; it++) {
        const int idx = it * 256 + tid;
        const int k = idx >> 5, j = idx & 31;
        sm[j * 257 + k] = Wout[(size_t)k * NPAR + n0 + j];
    }
    __syncthreads();

    const int j  = tid & 31;
    const int kq = tid >> 5;
    __nv_bfloat16* ph = g_Bh + (size_t)(n0 + j) * 256 + kq * 32;
    __nv_bfloat16* pl = g_Bl + (size_t)(n0 + j) * 256 + kq * 32;
    #pragma unroll
    for (int kk = 0; kk < 32; kk++) {
        const float w = sm[j * 257 + kq * 32 + kk];
        const __nv_bfloat16 hi = __float2bfloat16(w);
        const __nv_bfloat16 lo = __float2bfloat16(w - __bfloat162float(hi));
        ph[kk] = hi;
        pl[kk] = lo;
    }
}

// ===== Kernel A: cond path + dense_in + G = x_in @ Wk. 128 CTAs x 16 rows =====
__global__ __launch_bounds__(256) void kA(
    const float* __restrict__ actions, const float* __restrict__ obs,
    const float* __restrict__ Wci, const float* __restrict__ vci,
    const float* __restrict__ gci, const float* __restrict__ bci,
    const float* __restrict__ Wcl, const float* __restrict__ bcl,
    const float* __restrict__ Win, const float* __restrict__ vin,
    const float* __restrict__ gin, const float* __restrict__ bin,
    const float* __restrict__ Wk)
{
    __shared__ float sm1[16 * 256];
    __shared__ float sm2[16 * 256];
    const int tid = threadIdx.x;
    const int r0  = blockIdx.x * 16;

    { // t1 = actions @ Wci -> sm1[16][64]
        const int j = tid & 63, rr = tid >> 6;
        #pragma unroll
        for (int q = 0; q < 4; q++) {
            const int r = rr + q * 4;
            float acc = 0.f;
            #pragma unroll
            for (int k = 0; k < 16; k++)
                acc += actions[(r0 + r) * 16 + k] * Wci[k * 64 + j];
            sm1[r * 64 + j] = acc;
        }
    }
    __syncthreads();
    { // evonorm(groups=8) -> sm2[16][64]
        const int j = tid & 63, rr = tid >> 6;
        const float v = vci[j], g = gci[j], bb = bci[j];
        #pragma unroll
        for (int q = 0; q < 4; q++) {
            const int r = rr + q * 4;
            const float* row = &sm1[r * 64 + (j & ~7)];
            float s1 = 0.f, s2 = 0.f;
            #pragma unroll
            for (int e = 0; e < 8; e++) { float t = row[e]; s1 += t; s2 += t * t; }
            const float mean = s1 * 0.125f;
            const float var  = s2 * 0.125f - mean * mean;
            const float x = sm1[r * 64 + j];
            sm2[r * 64 + j] = x * sigf(v * x) / sqrtf(var + 1e-5f) * g + bb;
        }
    }
    __syncthreads();
    { // x = a1 @ Wcl + bcl + obs -> sm1[16][64]
        const int j = tid & 63, rr = tid >> 6;
        const float bj = bcl[j];
        float acc[4];
        #pragma unroll
        for (int q = 0; q < 4; q++)
            acc[q] = bj + obs[(r0 + rr + q * 4) * 64 + j];
        for (int k = 0; k < 64; k++) {
            const float w = Wcl[k * 64 + j];
            #pragma unroll
            for (int q = 0; q < 4; q++)
                acc[q] += sm2[(rr + q * 4) * 64 + k] * w;
        }
        #pragma unroll
        for (int q = 0; q < 4; q++)
            sm1[(rr + q * 4) * 64 + j] = acc[q];
    }
    __syncthreads();
    { // t2 = x @ Win -> sm2[16][256]
        const int j = tid;
        float acc[16];
        #pragma unroll
        for (int r = 0; r < 16; r++) acc[r] = 0.f;
        for (int k = 0; k < 64; k++) {
            const float w = Win[k * 256 + j];
            #pragma unroll
            for (int r = 0; r < 16; r++) acc[r] += sm1[r * 64 + k] * w;
        }
        #pragma unroll
        for (int r = 0; r < 16; r++) sm2[r * 256 + j] = acc[r];
    }
    __syncthreads();
    { // evonorm(group size 8) -> sm1[16][256]
        const int j = tid;
        const float v = vin[j], g = gin[j], bb = bin[j];
        for (int r = 0; r < 16; r++) {
            const float* row = &sm2[r * 256 + (j & ~7)];
            float s1 = 0.f, s2 = 0.f;
            #pragma unroll
            for (int e = 0; e < 8; e++) { float t = row[e]; s1 += t; s2 += t * t; }
            const float mean = s1 * 0.125f;
            const float var  = s2 * 0.125f - mean * mean;
            const float x = sm2[r * 256 + j];
            sm1[r * 256 + j] = x * sigf(v * x) / sqrtf(var + 1e-5f) * g + bb;
        }
    }
    __syncthreads();
    { // G = x_in @ Wk  (thread: 4 cols x 16 rows)
        const int c0 = tid * 4;
        float2 acc[16][2];
        #pragma unroll
        for (int r = 0; r < 16; r++) { acc[r][0] = make_float2(0.f,0.f); acc[r][1] = make_float2(0.f,0.f); }
        for (int k = 0; k < 256; k++) {
            const float4 w4 = *(const float4*)&Wk[k * 1024 + c0];
            const float2 wa = make_float2(w4.x, w4.y);
            const float2 wb = make_float2(w4.z, w4.w);
            #pragma unroll
            for (int r = 0; r < 16; r++) {
                const float x = sm1[r * 256 + k];
                const float2 xx = make_float2(x, x);
                acc[r][0] = fma2(wa, xx, acc[r][0]);
                acc[r][1] = fma2(wb, xx, acc[r][1]);
            }
        }
        #pragma unroll
        for (int r = 0; r < 16; r++) {
            float4 o;
            o.x = acc[r][0].x; o.y = acc[r][0].y; o.z = acc[r][1].x; o.w = acc[r][1].y;
            *(float4*)&g_G[(size_t)(r0 + r) * 1024 + c0] = o;
        }
    }
}

// ===== Kernel B: sequential LSTM, one 8-CTA cluster, 512 thr/CTA ============
__global__ void __launch_bounds__(512, 1) __cluster_dims__(8, 1, 1)
kB(const float* __restrict__ Wr, const float* __restrict__ vl_,
   const float* __restrict__ gl_, const float* __restrict__ bl_)
{
    __shared__ __align__(16) float s_h[256];
    __shared__ __align__(16) float s_z[2][128];

    const int tid = threadIdx.x;
    unsigned rank;
    asm("mov.u32 %0, %%cluster_ctarank;" : "=r"(rank));

    const int lcol  = tid >> 2;              // 0..127
    const int kpart = tid & 3;               // 0..3
    const int gcol  = (int)rank * 128 + lcol;
    const int k0    = kpart * 64;

    float2 wv[32];
    #pragma unroll
    for (int i = 0; i < 32; i++) {
        wv[i].x = Wr[(size_t)(k0 + 2*i)     * 1024 + gcol];
        wv[i].y = Wr[(size_t)(k0 + 2*i + 1) * 1024 + gcol];
    }

    float vl = 0.f, gl = 0.f, bl = 0.f, cst = 0.f;
    unsigned za0=0,za1=0,za2=0,za3=0, zb0=0,zb1=0,zb2=0,zb3=0;
    if (tid < 256) {
        vl = vl_[tid]; gl = gl_[tid]; bl = bl_[tid];
        #pragma unroll
        for (int g2 = 0; g2 < 4; g2++) {
            const int col = g2 * 256 + tid;
            const unsigned owner = (unsigned)(col >> 7);
            const unsigned local = (unsigned)(col & 127);
            unsigned la0 = smem_u32(&s_z[0][local]);
            unsigned la1 = smem_u32(&s_z[1][local]);
            unsigned ra0, ra1;
            asm("mapa.shared::cluster.u32 %0, %1, %2;" : "=r"(ra0) : "r"(la0), "r"(owner));
            asm("mapa.shared::cluster.u32 %0, %1, %2;" : "=r"(ra1) : "r"(la1), "r"(owner));
            if (g2 == 0) { za0 = ra0; zb0 = ra1; }
            if (g2 == 1) { za1 = ra0; zb1 = ra1; }
            if (g2 == 2) { za2 = ra0; zb2 = ra1; }
            if (g2 == 3) { za3 = ra0; zb3 = ra1; }
        }
        s_h[tid] = 0.f;
    }
    __syncthreads();

    int p = 0;
    for (int t = 0; t < NB; t++) {
        float gt = 0.f;
        if (kpart == 0) gt = g_G[(size_t)t * 1024 + gcol];

        float2 a0 = make_float2(0.f,0.f), a1 = make_float2(0.f,0.f);
        const float4* h4 = (const float4*)(s_h + k0);
        #pragma unroll
        for (int i = 0; i < 16; i++) {
            const float4 h = h4[i];
            a0 = fma2(wv[2*i],   make_float2(h.x, h.y), a0);
            a1 = fma2(wv[2*i+1], make_float2(h.z, h.w), a1);
        }
        float sum = a0.x + a0.y + a1.x + a1.y;
        sum += __shfl_xor_sync(0xffffffffu, sum, 1);
        sum += __shfl_xor_sync(0xffffffffu, sum, 2);
        if (kpart == 0) s_z[p][lcol] = sum + gt;

        asm volatile("barrier.cluster.arrive.aligned;" ::: "memory");
        asm volatile("barrier.cluster.wait.aligned;"   ::: "memory");

        if (tid < 256) {
            const unsigned ai = p ? zb0 : za0;
            const unsigned af = p ? zb1 : za1;
            const unsigned ac = p ? zb2 : za2;
            const unsigned ao = p ? zb3 : za3;
            float zi, zf, zc, zo;
            asm volatile("ld.shared::cluster.f32 %0, [%1];" : "=f"(zi) : "r"(ai));
            asm volatile("ld.shared::cluster.f32 %0, [%1];" : "=f"(zf) : "r"(af));
            asm volatile("ld.shared::cluster.f32 %0, [%1];" : "=f"(zc) : "r"(ac));
            asm volatile("ld.shared::cluster.f32 %0, [%1];" : "=f"(zo) : "r"(ao));

            float s1 = zc, s2 = zc * zc;
            s1 += __shfl_xor_sync(0xffffffffu, s1, 1);  s2 += __shfl_xor_sync(0xffffffffu, s2, 1);
            s1 += __shfl_xor_sync(0xffffffffu, s1, 2);  s2 += __shfl_xor_sync(0xffffffffu, s2, 2);
            s1 += __shfl_xor_sync(0xffffffffu, s1, 4);  s2 += __shfl_xor_sync(0xffffffffu, s2, 4);
            float mean = s1 * 0.125f;
            float var  = s2 * 0.125f - mean * mean;
            const float ecc = zc * sigf(vl * zc) / sqrtf(var + 1e-5f) * gl + bl;

            cst = sigf(zf) * cst + sigf(zi) * ecc;

            s1 = cst; s2 = cst * cst;
            s1 += __shfl_xor_sync(0xffffffffu, s1, 1);  s2 += __shfl_xor_sync(0xffffffffu, s2, 1);
            s1 += __shfl_xor_sync(0xffffffffu, s1, 2);  s2 += __shfl_xor_sync(0xffffffffu, s2, 2);
            s1 += __shfl_xor_sync(0xffffffffu, s1, 4);  s2 += __shfl_xor_sync(0xffffffffu, s2, 4);
            mean = s1 * 0.125f;
            var  = s2 * 0.125f - mean * mean;
            const float ecn = cst * sigf(vl * cst) / sqrtf(var + 1e-5f) * gl + bl;

            const float h = sigf(zo) * ecn;
            if (rank == 0) g_H[(size_t)t * 256 + tid] = h;
            s_h[tid] = h;
        }
        __syncthreads();
        p ^= 1;
    }
    asm volatile("barrier.cluster.arrive.aligned;" ::: "memory");
    asm volatile("barrier.cluster.wait.aligned;"   ::: "memory");
}

// ===== Kernel C: dense_0 + evonorm -> bf16 hi/lo split (g_Ah/g_Al) ==========
__global__ __launch_bounds__(256) void kC(
    const float* __restrict__ Wd0, const float* __restrict__ vd,
    const float* __restrict__ gd,  const float* __restrict__ bd)
{
    __shared__ float sm1[16 * 256];
    __shared__ float sm2[16 * 256];
    const int tid = threadIdx.x;
    const int r0  = blockIdx.x * 16;

    const float4* src = (const float4*)(g_H + (size_t)r0 * 256);
    for (int i = tid; i < 1024; i += 256)
        ((float4*)sm1)[i] = src[i];
    __syncthreads();

    const int j = tid;
    float acc[16];
    #pragma unroll
    for (int r = 0; r < 16; r++) acc[r] = 0.f;
    for (int k4 = 0; k4 < 64; k4++) {
        const int k = k4 * 4;
        const float w0 = Wd0[(k+0)*256 + j];
        const float w1 = Wd0[(k+1)*256 + j];
        const float w2 = Wd0[(k+2)*256 + j];
        const float w3 = Wd0[(k+3)*256 + j];
        #pragma unroll
        for (int r = 0; r < 16; r++) {
            const float4 x = *(const float4*)&sm1[r * 256 + k];
            acc[r] += x.x*w0 + x.y*w1 + x.z*w2 + x.w*w3;
        }
    }
    #pragma unroll
    for (int r = 0; r < 16; r++) sm2[r * 256 + j] = acc[r];
    __syncthreads();

    const float v = vd[j], g = gd[j], bb = bd[j];
    for (int r = 0; r < 16; r++) {
        const float* row = &sm2[r * 256 + (j & ~7)];
        float s1 = 0.f, s2 = 0.f;
        #pragma unroll
        for (int e = 0; e < 8; e++) { float t = row[e]; s1 += t; s2 += t * t; }
        const float mean = s1 * 0.125f;
        const float var  = s2 * 0.125f - mean * mean;
        const float x = sm2[r * 256 + j];
        const float y = x * sigf(v * x) / sqrtf(var + 1e-5f) * g + bb;
        const __nv_bfloat16 hi = __float2bfloat16(y);
        const __nv_bfloat16 lo = __float2bfloat16(y - __bfloat162float(hi));
        g_Ah[(size_t)(r0 + r) * 256 + j] = hi;
        g_Al[(size_t)(r0 + r) * 256 + j] = lo;
    }
}

// ===== Kernel D: HMMA bf16 3-split GEMM, CTA tile 128x128, serial K chunks ==
// Single 64 KB stage: Ah@0, Al@16K, Bh@32K, Bl@48K. 2 CTAs/SM give overlap.
#define KD_SMEM 65536

__global__ void __launch_bounds__(256, 2)
kD(const float* __restrict__ bout, float* __restrict__ out)
{
    extern __shared__ __align__(1024) char smem[];
    const uint32_t ST = smem_u32(smem);
    const int tid = threadIdx.x;
    const int wid = tid >> 5, lane = tid & 31;
    const int warp_m = wid & 1;      // 2 warps over M (64 rows each)
    const int warp_n = wid >> 1;     // 4 warps over N (32 cols each)
    const int n0 = blockIdx.x * 128;
    const int m0 = blockIdx.y * 128;

    const uint32_t a_row = warp_m * 64 + (lane & 15);
    const uint32_t a_kb  = (uint32_t)(lane >> 4) * 16;
    const uint32_t b_row = warp_n * 32 + (lane & 7) + ((lane >> 4) & 1) * 8;
    const uint32_t b_kb  = (uint32_t)((lane >> 3) & 1) * 16;

    float acc[4][4][4];   // [mblk][nblk][frag]
    #pragma unroll
    for (int i = 0; i < 4; i++)
        #pragma unroll
        for (int j = 0; j < 4; j++)
            #pragma unroll
            for (int q = 0; q < 4; q++) acc[i][j][q] = 0.f;

    for (int kc = 0; kc < 4; kc++) {
        const int koff = kc * 64;
        // ---- load chunk into the single stage ----
        #pragma unroll
        for (int sp = 0; sp < 2; sp++) {           // A hi/lo: 128 rows x 128B
            const __nv_bfloat16* gA = sp ? g_Al : g_Ah;
            const uint32_t db = ST + sp * 16384;
            #pragma unroll
            for (int i = 0; i < 4; i++) {
                const int g = tid + i * 256;
                const int row = g >> 3, j = g & 7;
                CP_ASYNC16(db + SWZ(row * 128 + j * 16),
                           gA + (size_t)(m0 + row) * 256 + koff + j * 8);
            }
        }
        #pragma unroll
        for (int sp = 0; sp < 2; sp++) {           // B hi/lo: 128 rows x 128B
            const __nv_bfloat16* gB = sp ? g_Bl : g_Bh;
            const uint32_t db = ST + 32768 + sp * 16384;
            #pragma unroll
            for (int i = 0; i < 4; i++) {
                const int g = tid + i * 256;
                const int row = g >> 3, j = g & 7;
                CP_ASYNC16(db + SWZ(row * 128 + j * 16),
                           gB + (size_t)(n0 + row) * 256 + koff + j * 8);
            }
        }
        CP_COMMIT();
        CP_WAIT_ALL();
        __syncthreads();

        // ---- compute chunk: 3 splits x 4 k16-steps ----
        #pragma unroll
        for (int split = 0; split < 3; split++) {
            const uint32_t Abase = ST + (split == 2 ? 16384u : 0u);
            const uint32_t Bbase = ST + 32768u + (split == 1 ? 16384u : 0u);
            #pragma unroll
            for (int ks = 0; ks < 4; ks++) {
                const uint32_t kk2 = (uint32_t)ks * 32;
                uint32_t af[4][4];
                #pragma unroll
                for (int mb = 0; mb < 4; mb++) {
                    const uint32_t addr = Abase + SWZ((a_row + mb * 16) * 128 + kk2 + a_kb);
                    LDSM_X4(af[mb][0], af[mb][1], af[mb][2], af[mb][3], addr);
                }
                uint32_t bfr[2][4];
                #pragma unroll
                for (int nb2 = 0; nb2 < 2; nb2++) {
                    const uint32_t addr = Bbase + SWZ((b_row + nb2 * 16) * 128 + kk2 + b_kb);
                    LDSM_X4(bfr[nb2][0], bfr[nb2][1], bfr[nb2][2], bfr[nb2][3], addr);
                }
                #pragma unroll
                for (int mb = 0; mb < 4; mb++) {
                    MMA16816(acc[mb][0], af[mb], bfr[0][0], bfr[0][1]);
                    MMA16816(acc[mb][1], af[mb], bfr[0][2], bfr[0][3]);
                    MMA16816(acc[mb][2], af[mb], bfr[1][0], bfr[1][1]);
                    MMA16816(acc[mb][3], af[mb], bfr[1][2], bfr[1][3]);
                }
            }
        }
        __syncthreads();
    }

    // ---- epilogue: direct float2 stores + bias ----
    #pragma unroll
    for (int nb = 0; nb < 4; nb++) {
        const int col = n0 + warp_n * 32 + nb * 8 + (lane & 3) * 2;
        const float2 bb = *(const float2*)&bout[col];
        #pragma unroll
        for (int mb = 0; mb < 4; mb++) {
            const int row = m0 + warp_m * 64 + mb * 16 + (lane >> 2);
            float2 v0, v1;
            v0.x = acc[mb][nb][0] + bb.x;  v0.y = acc[mb][nb][1] + bb.y;
            v1.x = acc[mb][nb][2] + bb.x;  v1.y = acc[mb][nb][3] + bb.y;
            *(float2*)&out[(size_t)row * NPAR + col]       = v0;
            *(float2*)&out[(size_t)(row + 8) * NPAR + col] = v1;
        }
    }
}

// ============================================================================
extern "C" void kernel_launch(void* const* d_in, const int* in_sizes, int n_in,
                              void* d_out, int out_size)
{
    const float* actions = (const float*)d_in[0];
    const float* obs     = (const float*)d_in[1];
    const float* Wci     = (const float*)d_in[2];
    const float* vci     = (const float*)d_in[3];
    const float* gci     = (const float*)d_in[4];
    const float* bci     = (const float*)d_in[5];
    const float* Wcl     = (const float*)d_in[6];
    const float* bcl     = (const float*)d_in[7];
    const float* Win     = (const float*)d_in[8];
    const float* vin     = (const float*)d_in[9];
    const float* gin     = (const float*)d_in[10];
    const float* bin     = (const float*)d_in[11];
    const float* Wk      = (const float*)d_in[12];
    const float* Wr      = (const float*)d_in[13];
    const float* vl      = (const float*)d_in[14];
    const float* gl      = (const float*)d_in[15];
    const float* bl      = (const float*)d_in[16];
    const float* Wd0     = (const float*)d_in[17];
    const float* vd0     = (const float*)d_in[18];
    const float* gd0     = (const float*)d_in[19];
    const float* bd0     = (const float*)d_in[20];
    const float* Wout    = (const float*)d_in[21];
    const float* bout    = (const float*)d_in[22];
    float* out = (float*)d_out;

    kW<<<NPAR / 32, 256>>>(Wout);
    kA<<<128, 256>>>(actions, obs, Wci, vci, gci, bci, Wcl, bcl,
                     Win, vin, gin, bin, Wk);
    kB<<<8, 512>>>(Wr, vl, gl, bl);
    kC<<<128, 256>>>(Wd0, vd0, gd0, bd0);

    cudaFuncSetAttribute(kD, cudaFuncAttributeMaxDynamicSharedMemorySize, KD_SMEM);
    dim3 gD(NPAR / 128, NB / 128);
    kD<<<gD, 256, KD_SMEM>>>(bout, out);
}